// round 1
// baseline (speedup 1.0000x reference)
#include <cuda_runtime.h>
#include <cstddef>

#define T_STEPS   4096
#define H_DIM     512
#define N_BATCH   32
#define V_DIM     3

#define GROUPS    4      // independent batch groups
#define BPG       8      // batches per group
#define COL_CTAS  32     // column CTAs per group
#define COLS      16     // H columns per CTA
#define NTHREADS  256
#define NWARPS    8
#define KCHUNK    (H_DIM / NWARPS)   // 64 k per warp

// ---- persistent scratch (no allocation allowed) ----
__device__ __align__(16) float g_state[GROUPS][H_DIM][BPG]; // [g][k][b], 64KB
__device__ int g_bar[GROUPS][T_STEPS];                      // per-group per-step arrive counters

// Reset per replay: zero barriers, state := 0.01
__global__ void esn_reset_kernel() {
    int idx = blockIdx.x * blockDim.x + threadIdx.x;
    // both arrays are exactly GROUPS*T_STEPS == GROUPS*H_DIM*BPG == 16384 elems
    ((int*)g_bar)[idx] = 0;
    ((float*)g_state)[idx] = 0.01f;
}

// dynamic smem layout (floats):
// [0, 4096)            s_sm[512][8]
// [4096, 12288)        Wsm[512][16]
// [12288, 13312)       red[8][8][16]
// [13312, 13360)       Win_sm[16][3]
#define SMEM_FLOATS (4096 + 8192 + 1024 + 48)
#define SMEM_BYTES  (SMEM_FLOATS * 4)

__global__ __launch_bounds__(NTHREADS, 1)
void esn_kernel(const float* __restrict__ X,
                const float* __restrict__ W_in,
                const float* __restrict__ W_int,
                const float* __restrict__ noise,
                float* __restrict__ out)
{
    extern __shared__ float smem[];
    float (*s_sm)[BPG]        = (float(*)[BPG])       (smem);
    float (*Wsm)[COLS]        = (float(*)[COLS])      (smem + 4096);
    float (*red)[BPG][COLS]   = (float(*)[BPG][COLS]) (smem + 4096 + 8192);
    float (*Win_sm)[V_DIM]    = (float(*)[V_DIM])     (smem + 4096 + 8192 + 1024);

    const int tid   = threadIdx.x;
    const int g     = blockIdx.x >> 5;        // batch group 0..3
    const int cbase = (blockIdx.x & 31) * COLS;
    const int w     = tid >> 5;               // warp -> k chunk
    const int lane  = tid & 31;
    const int bl    = lane >> 2;               // batch-in-group for compute (0..7)
    const int jq    = lane & 3;                // j quad (0..3)

    // ---- one-time loads (amortized over 4096 steps) ----
    for (int idx = tid; idx < H_DIM * COLS; idx += NTHREADS) {
        int k = idx >> 4, j = idx & 15;
        Wsm[k][j] = W_int[(size_t)k * H_DIM + cbase + j];
    }
    if (tid < COLS * V_DIM) {
        ((float*)Win_sm)[tid] = W_in[(size_t)cbase * V_DIM + tid];
    }
    __syncthreads();

    float* gstate = &g_state[g][0][0];

    // reducer-role constants (threads 0..127)
    const int rb = tid >> 4;             // batch-in-group
    const int rj = tid & 15;             // column-in-slice
    const int gb = g * BPG + rb;         // global batch
    const int h  = cbase + rj;           // global column
    float wi0 = 0.f, wi1 = 0.f, wi2 = 0.f;
    if (tid < 128) { wi0 = Win_sm[rj][0]; wi1 = Win_sm[rj][1]; wi2 = Win_sm[rj][2]; }

    for (int t = 0; t < T_STEPS; ++t) {
        // ---- prefetch noise & X (independent of state; issued before barrier) ----
        float nval = 0.f, x0 = 0.f, x1 = 0.f, x2 = 0.f;
        if (tid < 128) {
            nval = __ldg(noise + ((size_t)t * N_BATCH + gb) * H_DIM + h);
            const float* xp = X + ((size_t)gb * T_STEPS + t) * V_DIM;
            x0 = __ldg(xp + 0); x1 = __ldg(xp + 1); x2 = __ldg(xp + 2);
        }

        // ---- wait for state_{t-1} from all 32 CTAs in this group ----
        if (t > 0) {
            if (tid == 0) {
                const int* barp = &g_bar[g][t - 1];
                int v;
                do {
                    asm volatile("ld.acquire.gpu.global.b32 %0, [%1];"
                                 : "=r"(v) : "l"(barp) : "memory");
                } while (v < COL_CTAS);
            }
            __syncthreads();
        }

        // ---- per-warp state load (own k range only; bypass L1 via .cg) ----
        {
            const float4* src = (const float4*)gstate + w * 128 + lane;
            float4*       dst = (float4*)(&s_sm[0][0]) + w * 128 + lane;
            #pragma unroll
            for (int i = 0; i < 4; ++i) {
                float4 v4 = __ldcg(src + i * 32);
                dst[i * 32] = v4;
            }
            __syncwarp();
        }

        // ---- compute partials: lane owns (bl, j quad), warp owns k chunk ----
        float a0 = 0.f, a1 = 0.f, a2 = 0.f, a3 = 0.f;
        const int k0 = w * KCHUNK;
        #pragma unroll 16
        for (int kk = 0; kk < KCHUNK; ++kk) {
            const int k = k0 + kk;
            const float  sb = s_sm[k][bl];
            const float4 wv = *(const float4*)&Wsm[k][jq * 4];
            a0 += sb * wv.x;
            a1 += sb * wv.y;
            a2 += sb * wv.z;
            a3 += sb * wv.w;
        }
        *(float4*)&red[w][bl][jq * 4] = make_float4(a0, a1, a2, a3);
        __syncthreads();

        // ---- reduce, add input + noise, tanh, write ----
        if (tid < 128) {
            float sum = 0.f;
            #pragma unroll
            for (int ww = 0; ww < NWARPS; ++ww) sum += red[ww][rb][rj];
            float pre = sum + x0 * wi0 + x1 * wi1 + x2 * wi2 + 0.01f * nval;
            float sv  = tanhf(pre);
            gstate[h * BPG + rb] = sv;                                   // next-step state
            out[((size_t)gb * T_STEPS + t) * H_DIM + h] = sv;            // output (N,T,H)
        }
        __syncthreads();

        // ---- release arrive (cumulative: fence after CTA-wide sync) ----
        if (tid == 0) {
            __threadfence();
            atomicAdd(&g_bar[g][t], 1);
        }
    }
}

extern "C" void kernel_launch(void* const* d_in, const int* in_sizes, int n_in,
                              void* d_out, int out_size)
{
    const float* X     = (const float*)d_in[0];   // (32, 4096, 3)
    const float* W_in  = (const float*)d_in[1];   // (512, 3)
    const float* W_int = (const float*)d_in[2];   // (512, 512)
    const float* noise = (const float*)d_in[3];   // (4096, 32, 512)
    float* out = (float*)d_out;                   // (32, 4096, 512)

    cudaFuncSetAttribute(esn_kernel, cudaFuncAttributeMaxDynamicSharedMemorySize, SMEM_BYTES);

    esn_reset_kernel<<<32, 512>>>();
    esn_kernel<<<GROUPS * COL_CTAS, NTHREADS, SMEM_BYTES>>>(X, W_in, W_int, noise, out);
}

// round 2
// speedup vs baseline: 1.4923x; 1.4923x over previous
#include <cuda_runtime.h>
#include <cstddef>

#define T_STEPS   4096
#define H_DIM     512
#define N_BATCH   32
#define V_DIM     3

#define GROUPS    4      // independent batch groups
#define BPG       8      // batches per group
#define COL_CTAS  32     // column CTAs per group
#define COLS      16     // H columns per CTA
#define NTHREADS  256
#define NWARPS    8
#define KCHUNK    (H_DIM / NWARPS)   // 64 k per warp

// ---- persistent scratch (no allocation allowed) ----
__device__ __align__(16) float g_state[GROUPS][H_DIM][BPG]; // [g][k][b], 64KB
__device__ int g_bar[GROUPS][T_STEPS];                      // per-group per-step arrive counters

// Reset per replay: zero barriers, state := 0.01
__global__ void esn_reset_kernel() {
    int idx = blockIdx.x * blockDim.x + threadIdx.x;
    // both arrays are exactly GROUPS*T_STEPS == GROUPS*H_DIM*BPG == 16384 elems
    ((int*)g_bar)[idx] = 0;
    ((float*)g_state)[idx] = 0.01f;
}

// dynamic smem layout (floats):
// [0, 4096)            s_sm[512][8]
// [4096, 12288)        Wsm[512][16]
// [12288, 13312)       red[8][8][16]
// [13312, 13360)       Win_sm[16][3]
#define SMEM_FLOATS (4096 + 8192 + 1024 + 48)
#define SMEM_BYTES  (SMEM_FLOATS * 4)

__global__ __launch_bounds__(NTHREADS, 1)
void esn_kernel(const float* __restrict__ X,
                const float* __restrict__ W_in,
                const float* __restrict__ W_int,
                const float* __restrict__ noise,
                float* __restrict__ out)
{
    extern __shared__ float smem[];
    float (*s_sm)[BPG]        = (float(*)[BPG])       (smem);
    float (*Wsm)[COLS]        = (float(*)[COLS])      (smem + 4096);
    float (*red)[BPG][COLS]   = (float(*)[BPG][COLS]) (smem + 4096 + 8192);
    float (*Win_sm)[V_DIM]    = (float(*)[V_DIM])     (smem + 4096 + 8192 + 1024);

    const int tid   = threadIdx.x;
    const int g     = blockIdx.x >> 5;        // batch group 0..3
    const int cbase = (blockIdx.x & 31) * COLS;
    const int w     = tid >> 5;               // warp -> k chunk
    const int lane  = tid & 31;

    // compute-role lane decomposition: 4 cols x 2 batches x 2 k-halves
    const int jq = lane & 3;                  // column quad (4 cols)
    const int bp = (lane >> 2) & 3;           // batch pair (batches 2bp, 2bp+1)
    const int kh = lane >> 4;                 // k interleave half (0/1)
    const int k0 = w * KCHUNK;

    // ---- one-time loads (amortized over 4096 steps) ----
    for (int idx = tid; idx < H_DIM * COLS; idx += NTHREADS) {
        int k = idx >> 4, j = idx & 15;
        Wsm[k][j] = W_int[(size_t)k * H_DIM + cbase + j];
    }
    if (tid < COLS * V_DIM) {
        ((float*)Win_sm)[tid] = W_in[(size_t)cbase * V_DIM + tid];
    }
    __syncthreads();

    float* gstate = &g_state[g][0][0];
    const int* volatile barbase = &g_bar[g][0];

    // reducer-role constants (threads 0..127)
    const int rb = tid >> 4;             // batch-in-group
    const int rj = tid & 15;             // column-in-slice
    const int gb = g * BPG + rb;         // global batch
    const int h  = cbase + rj;           // global column
    float wi0 = 0.f, wi1 = 0.f, wi2 = 0.f;
    if (tid < 128) { wi0 = Win_sm[rj][0]; wi1 = Win_sm[rj][1]; wi2 = Win_sm[rj][2]; }

    // static compute-loop base pointers (in float4 / float2 units)
    const float4* wbase = (const float4*)(&Wsm[0][0]) + (size_t)(k0 + kh) * 4 + jq;
    const float2* sbase = (const float2*)(&s_sm[0][0]) + (size_t)(k0 + kh) * 4 + bp;

    for (int t = 0; t < T_STEPS; ++t) {
        // ---- prefetch noise & X (independent of state; issued before poll) ----
        float nval = 0.f, x0 = 0.f, x1 = 0.f, x2 = 0.f;
        if (tid < 128) {
            nval = __ldg(noise + ((size_t)t * N_BATCH + gb) * H_DIM + h);
            const float* xp = X + ((size_t)gb * T_STEPS + t) * V_DIM;
            x0 = __ldg(xp + 0); x1 = __ldg(xp + 1); x2 = __ldg(xp + 2);
        }

        // ---- per-warp acquire-poll: wait for state_{t-1} from all 32 CTAs ----
        if (t > 0) {
            const int* barp = &g_bar[g][t - 1];
            int v;
            do {
                asm volatile("ld.acquire.gpu.global.b32 %0, [%1];"
                             : "=r"(v) : "l"(barp) : "memory");
            } while (v < COL_CTAS);
        }

        // ---- per-warp state stage (own k range only; L2-resident via .cg) ----
        {
            const float4* src = (const float4*)gstate + w * 128 + lane;
            float4*       dst = (float4*)(&s_sm[0][0]) + w * 128 + lane;
            #pragma unroll
            for (int i = 0; i < 4; ++i) {
                float4 v4 = __ldcg(src + i * 32);
                dst[i * 32] = v4;
            }
            __syncwarp();
        }

        // ---- register-blocked partials: 8 acc = 2 batches x 4 cols ----
        float a00 = 0.f, a01 = 0.f, a02 = 0.f, a03 = 0.f;
        float a10 = 0.f, a11 = 0.f, a12 = 0.f, a13 = 0.f;
        #pragma unroll 8
        for (int kk = 0; kk < 32; ++kk) {
            const float4 wv = wbase[(size_t)kk * 8];   // W[k][jq*4..], k = k0+2kk+kh
            const float2 sv = sbase[(size_t)kk * 8];   // s[k][2bp..]
            a00 += sv.x * wv.x;  a01 += sv.x * wv.y;
            a02 += sv.x * wv.z;  a03 += sv.x * wv.w;
            a10 += sv.y * wv.x;  a11 += sv.y * wv.y;
            a12 += sv.y * wv.z;  a13 += sv.y * wv.w;
        }

        // merge the two k-halves (lane ^ 16)
        a00 += __shfl_xor_sync(0xffffffffu, a00, 16);
        a01 += __shfl_xor_sync(0xffffffffu, a01, 16);
        a02 += __shfl_xor_sync(0xffffffffu, a02, 16);
        a03 += __shfl_xor_sync(0xffffffffu, a03, 16);
        a10 += __shfl_xor_sync(0xffffffffu, a10, 16);
        a11 += __shfl_xor_sync(0xffffffffu, a11, 16);
        a12 += __shfl_xor_sync(0xffffffffu, a12, 16);
        a13 += __shfl_xor_sync(0xffffffffu, a13, 16);

        if (kh == 0) {
            *(float4*)&red[w][bp * 2 + 0][jq * 4] = make_float4(a00, a01, a02, a03);
            *(float4*)&red[w][bp * 2 + 1][jq * 4] = make_float4(a10, a11, a12, a13);
        }
        __syncthreads();

        // ---- reduce across 8 warps, add input + noise, tanh, write ----
        if (tid < 128) {
            float sum = 0.f;
            #pragma unroll
            for (int ww = 0; ww < NWARPS; ++ww) sum += red[ww][rb][rj];
            float pre = sum + x0 * wi0 + x1 * wi1 + x2 * wi2 + 0.01f * nval;
            float sv  = tanhf(pre);
            gstate[h * BPG + rb] = sv;                                   // next-step state
            out[((size_t)gb * T_STEPS + t) * H_DIM + h] = sv;            // output (N,T,H)
        }
        __syncthreads();

        // ---- release arrive (fence makes CTA's writes visible, then flag) ----
        if (tid == 0) {
            __threadfence();
            atomicAdd(&g_bar[g][t], 1);
        }
    }
    (void)barbase;
}

extern "C" void kernel_launch(void* const* d_in, const int* in_sizes, int n_in,
                              void* d_out, int out_size)
{
    const float* X     = (const float*)d_in[0];   // (32, 4096, 3)
    const float* W_in  = (const float*)d_in[1];   // (512, 3)
    const float* W_int = (const float*)d_in[2];   // (512, 512)
    const float* noise = (const float*)d_in[3];   // (4096, 32, 512)
    float* out = (float*)d_out;                   // (32, 4096, 512)

    cudaFuncSetAttribute(esn_kernel, cudaFuncAttributeMaxDynamicSharedMemorySize, SMEM_BYTES);

    esn_reset_kernel<<<32, 512>>>();
    esn_kernel<<<GROUPS * COL_CTAS, NTHREADS, SMEM_BYTES>>>(X, W_in, W_int, noise, out);
}